// round 1
// baseline (speedup 1.0000x reference)
#include <cuda_runtime.h>
#include <cuda_bf16.h>
#include <cstdint>

#define N_NODES 50000
#define FEATS   64
#define N_EDGES 800000
#define SCAN_B  1024
#define N_CHUNK ((N_NODES + SCAN_B - 1) / SCAN_B)   // 49

// -------- scratch (device globals; no allocation allowed) --------
__device__ int g_idx32;                 // 1 if indices are int32, 0 if int64
__device__ int g_deg[N_NODES];
__device__ int g_rowptr[N_NODES + 1];
__device__ int g_blocksum[64];
__device__ int g_blockoff[64];
__device__ int g_fill[N_NODES];
__device__ int g_col[N_EDGES];
__device__ __align__(16) float g_agg[N_NODES * FEATS];
__device__ __align__(16) float g_h1 [N_NODES * FEATS];
__device__ __align__(16) float g_h2 [N_NODES * FEATS];

// -------- dtype detection: item_ids == arange(N) --------
// int32 layout: words = 0,1,2,3,...  -> word[2] == 2
// int64 layout: words = 0,0,1,0,2,0  -> word[2] == 1
__global__ void k_detect(const int* ids_words) {
    g_idx32 = (ids_words[2] == 2) ? 1 : 0;
}

__global__ void k_zero() {
    int i = blockIdx.x * blockDim.x + threadIdx.x;
    if (i < N_NODES) { g_deg[i] = 0; g_fill[i] = 0; }
}

__device__ __forceinline__ int read_idx(const void* p, int i) {
    return g_idx32 ? ((const int*)p)[i] : (int)((const long long*)p)[i];
}

__global__ void k_degree(const void* __restrict__ dst) {
    int i = blockIdx.x * blockDim.x + threadIdx.x;
    if (i >= N_EDGES) return;
    atomicAdd(&g_deg[read_idx(dst, i)], 1);
}

// -------- 3-phase exclusive scan over g_deg -> g_rowptr --------
__global__ void k_scan1() {
    __shared__ int sh[SCAN_B];
    int tid = threadIdx.x;
    int gid = blockIdx.x * SCAN_B + tid;
    int v = (gid < N_NODES) ? g_deg[gid] : 0;
    sh[tid] = v;
    __syncthreads();
    #pragma unroll
    for (int off = 1; off < SCAN_B; off <<= 1) {
        int t = (tid >= off) ? sh[tid - off] : 0;
        __syncthreads();
        sh[tid] += t;
        __syncthreads();
    }
    if (gid < N_NODES) g_rowptr[gid + 1] = sh[tid];   // inclusive within chunk
    if (tid == SCAN_B - 1) g_blocksum[blockIdx.x] = sh[tid];
    if (gid == 0) g_rowptr[0] = 0;
}

__global__ void k_scan2(int nb) {
    __shared__ int sh[64];
    int tid = threadIdx.x;
    int v = (tid < nb) ? g_blocksum[tid] : 0;
    sh[tid] = v;
    __syncthreads();
    #pragma unroll
    for (int off = 1; off < 64; off <<= 1) {
        int t = (tid >= off) ? sh[tid - off] : 0;
        __syncthreads();
        sh[tid] += t;
        __syncthreads();
    }
    g_blockoff[tid] = sh[tid] - v;   // exclusive
}

__global__ void k_scan3() {
    int gid = blockIdx.x * SCAN_B + threadIdx.x;
    if (gid < N_NODES) g_rowptr[gid + 1] += g_blockoff[blockIdx.x];
}

__global__ void k_fill(const void* __restrict__ src, const void* __restrict__ dst) {
    int i = blockIdx.x * blockDim.x + threadIdx.x;
    if (i >= N_EDGES) return;
    int d = read_idx(dst, i);
    int s = read_idx(src, i);
    int pos = g_rowptr[d] + atomicAdd(&g_fill[d], 1);
    g_col[pos] = s;
}

// -------- mean aggregation: one warp per node, lane owns 2 feats --------
__global__ void k_agg(const float* __restrict__ h, float* __restrict__ agg) {
    int warp = (blockIdx.x * blockDim.x + threadIdx.x) >> 5;
    int lane = threadIdx.x & 31;
    if (warp >= N_NODES) return;
    int s = g_rowptr[warp], e = g_rowptr[warp + 1];
    const float2* h2 = (const float2*)h;
    float2 a0 = make_float2(0.f, 0.f), a1 = make_float2(0.f, 0.f);
    int j = s;
    for (; j + 1 < e; j += 2) {
        int c0 = g_col[j], c1 = g_col[j + 1];
        float2 v0 = h2[c0 * 32 + lane];
        float2 v1 = h2[c1 * 32 + lane];
        a0.x += v0.x; a0.y += v0.y;
        a1.x += v1.x; a1.y += v1.y;
    }
    if (j < e) {
        int c = g_col[j];
        float2 v = h2[c * 32 + lane];
        a0.x += v.x; a0.y += v.y;
    }
    int deg = e - s;
    float inv = (deg > 0) ? (1.0f / (float)deg) : 0.0f;
    float2 o;
    o.x = (a0.x + a1.x) * inv;
    o.y = (a0.y + a1.y) * inv;
    ((float2*)agg)[warp * 32 + lane] = o;
}

// -------- fused transform: C = act(H@Ws [+ G@Wn] + b), 64-node tiles --------
template <bool NEIGH, bool RELU>
__global__ void k_transform(const float* __restrict__ H, const float* __restrict__ G,
                            const float* __restrict__ Ws, const float* __restrict__ Wn,
                            const float* __restrict__ bias, float* __restrict__ C) {
    extern __shared__ float sm[];
    float* sWs = sm;                               // 4096 floats
    float* sWn = NEIGH ? (sm + 4096) : nullptr;    // 4096 floats
    float* sH  = NEIGH ? (sm + 8192) : (sm + 4096);
    float* sG  = NEIGH ? (sH + 4096) : nullptr;

    int tid = threadIdx.x;
    int n0 = blockIdx.x * 64;

    // load weights (1024 float4 each)
    #pragma unroll
    for (int i = 0; i < 4; i++) {
        int f = tid + i * 256;
        ((float4*)sWs)[f] = ((const float4*)Ws)[f];
        if (NEIGH) ((float4*)sWn)[f] = ((const float4*)Wn)[f];
    }
    // load node tiles (64 rows x 16 float4)
    #pragma unroll
    for (int i = 0; i < 4; i++) {
        int f = tid + i * 256;
        long g4 = (long)n0 * 16 + f;
        bool ok = (g4 < (long)N_NODES * 16);
        float4 v = ok ? ((const float4*)H)[g4] : make_float4(0.f, 0.f, 0.f, 0.f);
        ((float4*)sH)[f] = v;
        if (NEIGH) {
            float4 u = ok ? ((const float4*)G)[g4] : make_float4(0.f, 0.f, 0.f, 0.f);
            ((float4*)sG)[f] = u;
        }
    }
    __syncthreads();

    int tx = tid & 15;    // output group (4 outputs)
    int ty = tid >> 4;    // node group (4 nodes)

    float4 bv = ((const float4*)bias)[tx];
    float acc[4][4];
    #pragma unroll
    for (int i = 0; i < 4; i++) {
        acc[i][0] = bv.x; acc[i][1] = bv.y; acc[i][2] = bv.z; acc[i][3] = bv.w;
    }

    #pragma unroll 8
    for (int k = 0; k < 64; k++) {
        float4 ws = ((float4*)sWs)[k * 16 + tx];
        #pragma unroll
        for (int i = 0; i < 4; i++) {
            float hv = sH[(ty * 4 + i) * 64 + k];
            acc[i][0] += hv * ws.x;
            acc[i][1] += hv * ws.y;
            acc[i][2] += hv * ws.z;
            acc[i][3] += hv * ws.w;
        }
        if (NEIGH) {
            float4 wn = ((float4*)sWn)[k * 16 + tx];
            #pragma unroll
            for (int i = 0; i < 4; i++) {
                float gv = sG[(ty * 4 + i) * 64 + k];
                acc[i][0] += gv * wn.x;
                acc[i][1] += gv * wn.y;
                acc[i][2] += gv * wn.z;
                acc[i][3] += gv * wn.w;
            }
        }
    }

    #pragma unroll
    for (int i = 0; i < 4; i++) {
        int row = n0 + ty * 4 + i;
        if (row < N_NODES) {
            float4 o;
            o.x = RELU ? fmaxf(acc[i][0], 0.f) : acc[i][0];
            o.y = RELU ? fmaxf(acc[i][1], 0.f) : acc[i][1];
            o.z = RELU ? fmaxf(acc[i][2], 0.f) : acc[i][2];
            o.w = RELU ? fmaxf(acc[i][3], 0.f) : acc[i][3];
            ((float4*)C)[row * 16 + tx] = o;
        }
    }
}

extern "C" void kernel_launch(void* const* d_in, const int* in_sizes, int n_in,
                              void* d_out, int out_size) {
    const float* embed   = (const float*)d_in[0];
    const float* W1_self = (const float*)d_in[1];
    const float* W1_neigh= (const float*)d_in[2];
    const float* b1      = (const float*)d_in[3];
    const float* W2_self = (const float*)d_in[4];
    const float* W2_neigh= (const float*)d_in[5];
    const float* b2      = (const float*)d_in[6];
    const float* W_fc    = (const float*)d_in[7];
    const float* b_fc    = (const float*)d_in[8];
    const int*   ids_w   = (const int*)d_in[9];    // raw words; dtype detected on device
    const void*  src     = d_in[10];
    const void*  dst     = d_in[11];
    float* out = (float*)d_out;

    // opt-in to >48KB dynamic smem (host API, executes immediately — not a graph op)
    cudaFuncSetAttribute((const void*)k_transform<true, true>,
                         cudaFuncAttributeMaxDynamicSharedMemorySize, 64 * 1024);
    cudaFuncSetAttribute((const void*)k_transform<true, false>,
                         cudaFuncAttributeMaxDynamicSharedMemorySize, 64 * 1024);
    cudaFuncSetAttribute((const void*)k_transform<false, false>,
                         cudaFuncAttributeMaxDynamicSharedMemorySize, 32 * 1024);

    float* agg; cudaGetSymbolAddress((void**)&agg, g_agg);
    float* h1;  cudaGetSymbolAddress((void**)&h1,  g_h1);
    float* h2;  cudaGetSymbolAddress((void**)&h2,  g_h2);

    // --- CSR build (once, reused by both layers) ---
    k_detect<<<1, 1>>>(ids_w);
    k_zero<<<(N_NODES + 255) / 256, 256>>>();
    k_degree<<<(N_EDGES + 255) / 256, 256>>>(dst);
    k_scan1<<<N_CHUNK, SCAN_B>>>();
    k_scan2<<<1, 64>>>(N_CHUNK);
    k_scan3<<<N_CHUNK, SCAN_B>>>();
    k_fill<<<(N_EDGES + 255) / 256, 256>>>(src, dst);

    const int AGG_BLOCKS = (N_NODES * 32 + 255) / 256;
    const int GEMM_BLOCKS = (N_NODES + 63) / 64;

    // --- Layer 1: agg(x) then relu(x@W1s + agg@W1n + b1) ---
    k_agg<<<AGG_BLOCKS, 256>>>(embed, agg);
    k_transform<true, true><<<GEMM_BLOCKS, 256, 64 * 1024>>>(
        embed, agg, W1_self, W1_neigh, b1, h1);

    // --- Layer 2: agg(h1) then h1@W2s + agg@W2n + b2 (no relu) ---
    k_agg<<<AGG_BLOCKS, 256>>>(h1, agg);
    k_transform<true, false><<<GEMM_BLOCKS, 256, 64 * 1024>>>(
        h1, agg, W2_self, W2_neigh, b2, h2);

    // --- Final linear: out = h2@W_fc + b_fc ---
    k_transform<false, false><<<GEMM_BLOCKS, 256, 32 * 1024>>>(
        h2, nullptr, W_fc, nullptr, b_fc, out);
}